// round 12
// baseline (speedup 1.0000x reference)
#include <cuda_runtime.h>
#include <cuda_fp16.h>
#include <cstdint>
#include <math.h>

// Problem dims
#define HW   32768
#define CCH  256
#define HH   128
#define WWD  256
#define NPIX 65536      // B * HW
#define PPTS 9
#define GRP  8

#define PADM 136        // tf32 SMEM row stride (floats)
#define PADK 40         // f16 SMEM row stride (halves)

// ---------------- scratch (static device globals; no allocation) ------------
__device__ __half g_value[(size_t)NPIX * CCH];    // (pixel, j) fp16
__device__ float  g_logits[(size_t)NPIX * 128];   // cols 0..71 consumed
__device__ __half g_agg[(size_t)NPIX * CCH];      // fp16
__device__ float  g_W2v[CCH * 256];               // tf32(gamma2*Wv) [c][j]
__device__ float  g_W2w[CCH * 128];               // tf32(gamma1*[Ww|Wk|0]) [c][j]
__device__ __half g_WoT[256 * 256];               // Wo^T fp16 [j][c]
__device__ float  g_uv[256], g_vv[256];           // mode0 epilogue vectors
__device__ float  g_uw[128], g_vw[128];           // mode1 epilogue vectors
__device__ float  g_cA[16], g_cB[16];             // offset epilogue constants

__device__ __forceinline__ uint32_t f2tf32(float f) {
    uint32_t r;
    asm("cvt.rna.tf32.f32 %0, %1;" : "=r"(r) : "f"(f));
    return r;
}
__device__ __forceinline__ uint32_t smem_u32(const void* p) {
    uint32_t a;
    asm("{ .reg .u64 t; cvta.to.shared.u64 t, %1; cvt.u32.u64 %0, t; }" : "=r"(a) : "l"(p));
    return a;
}
#define CP16(dst, src) \
    asm volatile("cp.async.cg.shared.global [%0], [%1], 16;" :: "r"(dst), "l"(src))
#define CPCOMMIT() asm volatile("cp.async.commit_group;" ::)
#define CPWAIT1()  asm volatile("cp.async.wait_group 1;" ::)

__device__ __forceinline__ float wpad_val(const float* __restrict__ Ww,
                                          const float* __restrict__ Wk,
                                          int c, int j) {
    if (j < 72) return Ww[c * 72 + j];
    if (j < 81) return Wk[c * 9 + (j - 72)];
    return 0.f;
}

// ---------------- K2: single fused prep (weight images + epilogue vectors) --
__global__ __launch_bounds__(256) void prep_all(const float* __restrict__ Wv,
                                                const float* __restrict__ g2,
                                                const float* __restrict__ b2,
                                                const float* __restrict__ bv,
                                                const float* __restrict__ Wo,
                                                const float* __restrict__ g1,
                                                const float* __restrict__ b1,
                                                const float* __restrict__ Ww,
                                                const float* __restrict__ bw,
                                                const float* __restrict__ Wk,
                                                const float* __restrict__ bk) {
    const int bx = blockIdx.x, t = threadIdx.x;
    if (bx < 256) {
        const int e = bx * 256 + t;
        { const int c = e >> 8;
          g_W2v[e] = __uint_as_float(f2tf32(g2[c] * Wv[e])); }
        { const int j = e >> 8, c = e & 255;
          g_WoT[e] = __float2half(Wo[c * 256 + j]); }
        if (e < CCH * 128) {
            const int c = e >> 7, j = e & 127;
            g_W2w[e] = __uint_as_float(f2tf32(g1[c] * wpad_val(Ww, Wk, c, j)));
        }
    } else if (bx == 256) {
        float u = 0.f, v = 0.f;
        for (int c = 0; c < CCH; ++c) {
            const float w = Wv[c * 256 + t];
            u = fmaf(g2[c], w, u);
            v = fmaf(b2[c], w, v);
        }
        g_uv[t] = u; g_vv[t] = v + bv[t];
    } else {
        if (t < 128) {
            float u = 0.f, v = 0.f;
            for (int c = 0; c < CCH; ++c) {
                const float w = wpad_val(Ww, Wk, c, t);
                u = fmaf(g1[c], w, u);
                v = fmaf(b1[c], w, v);
            }
            const float bp = (t < 72) ? bw[t] : ((t < 81) ? bk[t - 72] : 0.f);
            g_uw[t] = u; g_vw[t] = v + bp;
        } else if (t < 128 + PPTS) {
            const int p = t - 128;
            float a = 0.f, bs = 0.f;
            for (int c = 0; c < CCH; ++c) {
                a  = fmaf(b1[c], Wk[c * PPTS + p], a);
                bs = fmaf(g1[c], Wk[c * PPTS + p], bs);
            }
            g_cA[p] = a + bk[p];
            g_cB[p] = bs;
        }
    }
}

// ---------------- K3: tf32 GEMM, cp.async pipeline, fused LN stats ----------
// Grid is (j_tiles, m_tiles): the CTAs sharing one A slab are ADJACENT in
// linear launch order, so the 2nd one's feats loads hit L2 (halves DRAM).
// MODE 0 (3-stage): g_value[m, j0+j] = rstd*(x2 @ W2v) - rstd*mean*u + v
// MODE 1 (2-stage): g_logits + fp32 keypoint offsets -> kp_out
template <int MODE>
__global__ __launch_bounds__(256, 2) void gemm_tf32(const float* __restrict__ feats,
                                                    const float* __restrict__ Wk,
                                                    const float* __restrict__ gamma1,
                                                    const float* __restrict__ anchor,
                                                    float* __restrict__ kp_out) {
    extern __shared__ char smem_raw[];
    const int STG = 32 * PADM;                       // floats per stage matrix
    const int NSTG = (MODE == 0) ? 3 : 2;
    float* Asf = reinterpret_cast<float*>(smem_raw);
    float* Bsf = Asf + NSTG * STG;
    float* mean_s = Bsf + NSTG * STG;
    float* rstd_s = mean_s + 128;
    float* u_s = rstd_s + 128;
    float* v_s = u_s + 128;
    float* red1 = v_s + 128;    // 256
    float* red2 = red1 + 256;   // 256
    float* wk_s = red2 + 256;   // MODE1: 2304
    float* cA_s = wk_s + 2304;  // 16
    float* cB_s = cA_s + 16;    // 16

    const float* W2   = (MODE == 0) ? g_W2v : g_W2w;
    const float* uvec = (MODE == 0) ? g_uv : g_uw;
    const float* vvec = (MODE == 0) ? g_vv : g_vw;

    const int t = threadIdx.x, lane = t & 31, wid = t >> 5;
    const int lk = lane & 3, lr = lane >> 2;
    const int mb = (wid & 1) * 64, nb = (wid >> 1) * 32;

    const int m0 = blockIdx.y * 128, j0 = blockIdx.x * 128;
    const int b = m0 >> 15, n0 = m0 & (HW - 1);
    const int LDB = (MODE == 0) ? 256 : 128;

    if (t < 128) {
        u_s[t] = uvec[j0 + t];
        v_s[t] = vvec[j0 + t];
    }
    if (MODE == 1) {
        for (int idx = t; idx < CCH * PPTS; idx += 256) {
            const int c = idx / PPTS;
            wk_s[idx] = gamma1[c] * Wk[idx];
        }
        if (t < PPTS) { cA_s[t] = g_cA[t]; cB_s[t] = g_cB[t]; }
    }

    const float* fb = feats + ((size_t)b << 23) + n0;
    const uint32_t sbA = smem_u32(Asf);
    const uint32_t sbB = smem_u32(Bsf);
    const int fc0 = t >> 5;              // 0..7
    const int fm4 = (t & 31) << 2;       // 0..124

    auto fill = [&](int s, int kt) {
        const int k0 = kt * 32;
        const uint32_t aoff = sbA + (uint32_t)s * STG * 4;
        const uint32_t boff = sbB + (uint32_t)s * STG * 4;
#pragma unroll
        for (int i = 0; i < 4; ++i) {
            const int c = fc0 + i * 8;
            CP16(aoff + (uint32_t)(c * PADM + fm4) * 4,
                 fb + ((size_t)(k0 + c) << 15) + fm4);
            CP16(boff + (uint32_t)(c * PADM + fm4) * 4,
                 W2 + (size_t)(k0 + c) * LDB + j0 + fm4);
        }
    };

    float acc[4][4][4];
#pragma unroll
    for (int mi = 0; mi < 4; ++mi)
#pragma unroll
        for (int ni = 0; ni < 4; ++ni)
#pragma unroll
            for (int q = 0; q < 4; ++q) acc[mi][ni][q] = 0.f;

    // in-kernel LN stats (+offsets for MODE 1)
    float s1 = 0.f, s2acc = 0.f;
    float o[PPTS];
#pragma unroll
    for (int p = 0; p < PPTS; ++p) o[p] = 0.f;
    const int sm = t & 127, sh = (t >> 7) << 4;   // row, k-half offset

    auto do_mma = [&](const float* Ast, const float* Bst) {
        const uint32_t* As = reinterpret_cast<const uint32_t*>(Ast);
        const uint32_t* Bs = reinterpret_cast<const uint32_t*>(Bst);
#pragma unroll
        for (int ks = 0; ks < 4; ++ks) {
            const int kb = ks * 8;
            uint32_t a[4][4];
#pragma unroll
            for (int mi = 0; mi < 4; ++mi) {
                const uint32_t* Ab = &As[(kb + lk) * PADM + mb + 16 * mi + lr];
                a[mi][0] = Ab[0];
                a[mi][1] = Ab[8];
                a[mi][2] = Ab[4 * PADM];
                a[mi][3] = Ab[4 * PADM + 8];
            }
            uint32_t bf[4][2];
#pragma unroll
            for (int ni = 0; ni < 4; ++ni) {
                const uint32_t* Bb = &Bs[(kb + lk) * PADM + nb + 8 * ni + lr];
                bf[ni][0] = Bb[0];
                bf[ni][1] = Bb[4 * PADM];
            }
#pragma unroll
            for (int mi = 0; mi < 4; ++mi)
#pragma unroll
                for (int ni = 0; ni < 4; ++ni) {
                    asm volatile(
                        "mma.sync.aligned.m16n8k8.row.col.f32.tf32.tf32.f32 "
                        "{%0,%1,%2,%3}, {%4,%5,%6,%7}, {%8,%9}, {%0,%1,%2,%3};"
                        : "+f"(acc[mi][ni][0]), "+f"(acc[mi][ni][1]),
                          "+f"(acc[mi][ni][2]), "+f"(acc[mi][ni][3])
                        : "r"(a[mi][0]), "r"(a[mi][1]), "r"(a[mi][2]), "r"(a[mi][3]),
                          "r"(bf[ni][0]), "r"(bf[ni][1]));
                }
        }
    };

    if (MODE == 0) {
        fill(0, 0); CPCOMMIT();
        fill(1, 1); CPCOMMIT();
        for (int kt = 0; kt < 8; ++kt) {
            CPWAIT1();
            __syncthreads();
            if (kt + 2 < 8) fill((kt + 2) % 3, kt + 2);
            CPCOMMIT();
            const float* Ast = Asf + (kt % 3) * STG;
#pragma unroll
            for (int cc = 0; cc < 16; ++cc) {
                const float v = Ast[(sh + cc) * PADM + sm];
                s1 += v; s2acc = fmaf(v, v, s2acc);
            }
            do_mma(Ast, Bsf + (kt % 3) * STG);
        }
    } else {
        fill(0, 0); CPCOMMIT();
        for (int kt = 0; kt < 8; ++kt) {
            if (kt + 1 < 8) fill((kt + 1) & 1, kt + 1);
            CPCOMMIT();
            CPWAIT1();
            __syncthreads();
            const float* Ast = Asf + (kt & 1) * STG;
#pragma unroll
            for (int cc = 0; cc < 16; ++cc) {
                const float v = Ast[(sh + cc) * PADM + sm];
                s1 += v; s2acc = fmaf(v, v, s2acc);
                const float* wrow = wk_s + (kt * 32 + sh + cc) * PPTS;
#pragma unroll
                for (int p = 0; p < PPTS; ++p)
                    o[p] = fmaf(v, wrow[p], o[p]);
            }
            do_mma(Ast, Bsf + (kt & 1) * STG);
            __syncthreads();
        }
    }

    // ---- reduce LN stats ----
    red1[t] = s1; red2[t] = s2acc;
    __syncthreads();
    if (t < 128) {
        const float S1 = red1[t] + red1[t + 128];
        const float S2 = red2[t] + red2[t + 128];
        const float m = S1 * (1.f / 256.f);
        mean_s[t] = m;
        rstd_s[t] = rsqrtf(S2 * (1.f / 256.f) - m * m + 1e-5f);
    }
    __syncthreads();

    // ---- MODE 1: reduce offsets, emit keypoints ----
    if (MODE == 1) {
        float ax = 0.f, ay = 0.f;
        if (t < 128) {
            ax = anchor[2 * (m0 + t)];
            ay = anchor[2 * (m0 + t) + 1];
        }
#pragma unroll
        for (int p = 0; p < PPTS; ++p) {
            red1[t] = o[p];
            __syncthreads();
            if (t < 128) {
                const float S = red1[t] + red1[t + 128];
                const float off = rstd_s[t] * (S - mean_s[t] * cB_s[p]) + cA_s[p];
                kp_out[((size_t)(m0 + t) * PPTS + p) * 2]     = ax + off;
                kp_out[((size_t)(m0 + t) * PPTS + p) * 2 + 1] = ay;
            }
            __syncthreads();
        }
    }

    // ---- epilogue: C = rstd*D - rstd*mean*u + v ----
#pragma unroll
    for (int mi = 0; mi < 4; ++mi) {
        const int ml = mb + 16 * mi + lr;
        const float r0 = rstd_s[ml],     rm0 = r0 * mean_s[ml];
        const float r1 = rstd_s[ml + 8], rm1 = r1 * mean_s[ml + 8];
#pragma unroll
        for (int ni = 0; ni < 4; ++ni) {
            const int jc = nb + 8 * ni + 2 * lk;
            const float u0 = u_s[jc], u1 = u_s[jc + 1];
            const float v0 = v_s[jc], v1 = v_s[jc + 1];
            const float c00 = fmaf(r0, acc[mi][ni][0], fmaf(-rm0, u0, v0));
            const float c01 = fmaf(r0, acc[mi][ni][1], fmaf(-rm0, u1, v1));
            const float c10 = fmaf(r1, acc[mi][ni][2], fmaf(-rm1, u0, v0));
            const float c11 = fmaf(r1, acc[mi][ni][3], fmaf(-rm1, u1, v1));
            if (MODE == 0) {
                const __half2 h0 = __floats2half2_rn(c00, c01);
                const __half2 h1 = __floats2half2_rn(c10, c11);
                *reinterpret_cast<__half2*>(g_value + (size_t)(m0 + ml) * 256 + j0 + jc) = h0;
                *reinterpret_cast<__half2*>(g_value + (size_t)(m0 + ml + 8) * 256 + j0 + jc) = h1;
            } else if (jc < 72) {
                float2 r0v; r0v.x = c00; r0v.y = c01;
                float2 r1v; r1v.x = c10; r1v.y = c11;
                *reinterpret_cast<float2*>(g_logits + (size_t)(m0 + ml) * 128 + jc) = r0v;
                *reinterpret_cast<float2*>(g_logits + (size_t)(m0 + ml + 8) * 128 + jc) = r1v;
            }
        }
    }
}

// ---------------- K6: fp16 GEMM (out = Wo^T @ agg^T + bo), cp.async 3-stage -
// Grid (j_tiles, n_tiles): CTAs sharing an agg slab are adjacent -> L2 reuse.
__global__ __launch_bounds__(256, 2) void gemm_f16(const float* __restrict__ bias,
                                                   float* __restrict__ out) {
    extern __shared__ char smem_raw[];
    const int STGH = 128 * PADK;                        // halves per stage matrix
    __half* Ash = reinterpret_cast<__half*>(smem_raw);  // 3 stages (Wo^T tile)
    __half* Bsh = Ash + 3 * STGH;                       // 3 stages (agg tile)

    const int t = threadIdx.x, lane = t & 31, wid = t >> 5;
    const int lk = lane & 3, lr = lane >> 2;
    const int mb = (wid & 1) * 64, nb = (wid >> 1) * 32;

    const int n0 = blockIdx.y * 128, j0 = blockIdx.x * 128;
    const int b = n0 >> 15, nbase = n0 & (HW - 1);

    const uint32_t sbA = smem_u32(Ash);
    const uint32_t sbB = smem_u32(Bsh);

    auto fill = [&](int s, int kt) {
        const int k0 = kt * 32;
#pragma unroll
        for (int i = 0; i < 2; ++i) {
            const int idx = t + i * 256;
            const int row = idx >> 2, seg = (idx & 3) << 3;   // seg in halves
            CP16(sbA + (uint32_t)s * STGH * 2 + (uint32_t)(row * PADK + seg) * 2,
                 g_WoT + (size_t)(j0 + row) * 256 + k0 + seg);
            CP16(sbB + (uint32_t)s * STGH * 2 + (uint32_t)(row * PADK + seg) * 2,
                 g_agg + ((size_t)(n0 + row) << 8) + k0 + seg);
        }
    };

    float acc[4][4][4];
#pragma unroll
    for (int mi = 0; mi < 4; ++mi)
#pragma unroll
        for (int ni = 0; ni < 4; ++ni)
#pragma unroll
            for (int q = 0; q < 4; ++q) acc[mi][ni][q] = 0.f;

    fill(0, 0); CPCOMMIT();
    fill(1, 1); CPCOMMIT();

    for (int kt = 0; kt < 8; ++kt) {
        CPWAIT1();
        __syncthreads();
        if (kt + 2 < 8) fill((kt + 2) % 3, kt + 2);
        CPCOMMIT();

        const __half* At = Ash + (kt % 3) * STGH;
        const __half* Bt = Bsh + (kt % 3) * STGH;
#pragma unroll
        for (int ks = 0; ks < 2; ++ks) {
            const int kk = ks * 16 + lk * 2;
            uint32_t a[4][4];
#pragma unroll
            for (int mi = 0; mi < 4; ++mi) {
                const __half* Ab = At + (mb + 16 * mi + lr) * PADK + kk;
                a[mi][0] = *reinterpret_cast<const uint32_t*>(Ab);
                a[mi][1] = *reinterpret_cast<const uint32_t*>(Ab + 8 * PADK);
                a[mi][2] = *reinterpret_cast<const uint32_t*>(Ab + 8);
                a[mi][3] = *reinterpret_cast<const uint32_t*>(Ab + 8 * PADK + 8);
            }
            uint32_t bf[4][2];
#pragma unroll
            for (int ni = 0; ni < 4; ++ni) {
                const __half* Bb = Bt + (nb + 8 * ni + lr) * PADK + kk;
                bf[ni][0] = *reinterpret_cast<const uint32_t*>(Bb);
                bf[ni][1] = *reinterpret_cast<const uint32_t*>(Bb + 8);
            }
#pragma unroll
            for (int mi = 0; mi < 4; ++mi)
#pragma unroll
                for (int ni = 0; ni < 4; ++ni) {
                    asm volatile(
                        "mma.sync.aligned.m16n8k16.row.col.f32.f16.f16.f32 "
                        "{%0,%1,%2,%3}, {%4,%5,%6,%7}, {%8,%9}, {%0,%1,%2,%3};"
                        : "+f"(acc[mi][ni][0]), "+f"(acc[mi][ni][1]),
                          "+f"(acc[mi][ni][2]), "+f"(acc[mi][ni][3])
                        : "r"(a[mi][0]), "r"(a[mi][1]), "r"(a[mi][2]), "r"(a[mi][3]),
                          "r"(bf[ni][0]), "r"(bf[ni][1]));
                }
        }
    }

    // ---- epilogue: out[b][j][n] ----
#pragma unroll
    for (int mi = 0; mi < 4; ++mi) {
        const int j = j0 + mb + 16 * mi + lr;
        const float br0 = __ldg(bias + j);
        const float br1 = __ldg(bias + j + 8);
        float* d0 = out + (((size_t)(b * CCH + j)) << 15) + nbase;
        float* d1 = out + (((size_t)(b * CCH + j + 8)) << 15) + nbase;
#pragma unroll
        for (int ni = 0; ni < 4; ++ni) {
            const int cb = nb + 8 * ni + 2 * lk;
            float2 r0, r1;
            r0.x = acc[mi][ni][0] + br0;
            r0.y = acc[mi][ni][1] + br0;
            r1.x = acc[mi][ni][2] + br1;
            r1.y = acc[mi][ni][3] + br1;
            *reinterpret_cast<float2*>(d0 + cb) = r0;
            *reinterpret_cast<float2*>(d1 + cb) = r1;
        }
    }
}

// ---------------- K5: fused softmax + gather, precomputed taps + fp16 blend -
__global__ __launch_bounds__(256) void agg_kernel(const float* __restrict__ kp) {
    __shared__ float  w_s[8][72];
    __shared__ int4   soff[8][PPTS];     // byte offsets of the 4 taps (0 if OOB)
    __shared__ float4 swgt[8][PPTS];     // tap weights (0 if OOB)

    const int t = threadIdx.x;
    const int pg0 = blockIdx.x << 3;

    if (t < 64) {
        const int lp = t >> 3, g = t & 7;
        const float* row = g_logits + (size_t)(pg0 + lp) * 128 + g;
        float l[PPTS];
        float mx = -1e30f;
#pragma unroll
        for (int p = 0; p < PPTS; ++p) { l[p] = row[p * 8]; mx = fmaxf(mx, l[p]); }
        float s = 0.f;
#pragma unroll
        for (int p = 0; p < PPTS; ++p) { l[p] = __expf(l[p] - mx); s += l[p]; }
        const float inv = 1.f / s;
#pragma unroll
        for (int p = 0; p < PPTS; ++p) w_s[lp][p * 8 + g] = l[p] * inv;
    }
    if (t >= 128 && t < 128 + 8 * PPTS) {
        const int idx = t - 128;
        const int lp = idx / PPTS, p = idx - lp * PPTS;
        const size_t kidx = ((size_t)(pg0 + lp) * PPTS + p) * 2;
        const float x = kp[kidx] * (float)WWD - 0.5f;
        const float y = kp[kidx + 1] * (float)HH - 0.5f;
        const float xf = floorf(x), yf = floorf(y);
        const int x0 = (int)xf, y0 = (int)yf;
        const float wx = x - xf, wy = y - yf;
        const bool xv0 = (x0 >= 0) & (x0 < WWD);
        const bool xv1 = (x0 + 1 >= 0) & (x0 + 1 < WWD);
        const bool yv0 = (y0 >= 0) & (y0 < HH);
        const bool yv1 = (y0 + 1 >= 0) & (y0 + 1 < HH);
        int4 off;
        off.x = (yv0 && xv0) ? ((y0 * WWD + x0) << 9) : 0;
        off.y = (yv0 && xv1) ? ((y0 * WWD + x0 + 1) << 9) : 0;
        off.z = (yv1 && xv0) ? (((y0 + 1) * WWD + x0) << 9) : 0;
        off.w = (yv1 && xv1) ? (((y0 + 1) * WWD + x0 + 1) << 9) : 0;
        float4 wt;
        wt.x = (yv0 && xv0) ? (1.f - wx) * (1.f - wy) : 0.f;
        wt.y = (yv0 && xv1) ? wx * (1.f - wy) : 0.f;
        wt.z = (yv1 && xv0) ? (1.f - wx) * wy : 0.f;
        wt.w = (yv1 && xv1) ? wx * wy : 0.f;
        soff[lp][p] = off;
        swgt[lp][p] = wt;
    }
    __syncthreads();

    const int lp = t >> 5, lane = t & 31;
    const int c = lane << 3;          // 8 channels / thread
    const int g = lane >> 2;
    const int pg = pg0 + lp, b = pg >> 15;
    const char* vbb = reinterpret_cast<const char*>(g_value + ((size_t)b << 23) + c);

    float fa[8];
#pragma unroll
    for (int q = 0; q < 8; ++q) fa[q] = 0.f;

#pragma unroll
    for (int p = 0; p < PPTS; ++p) {
        const int4 off = soff[lp][p];
        const float4 wt = swgt[lp][p];
        const float wp = w_s[lp][p * 8 + g];
        const __half2 hw00 = __float2half2_rn(wp * wt.x);
        const __half2 hw01 = __float2half2_rn(wp * wt.y);
        const __half2 hw10 = __float2half2_rn(wp * wt.z);
        const __half2 hw11 = __float2half2_rn(wp * wt.w);
        const uint4 r00 = *reinterpret_cast<const uint4*>(vbb + off.x);
        const uint4 r01 = *reinterpret_cast<const uint4*>(vbb + off.y);
        const uint4 r10 = *reinterpret_cast<const uint4*>(vbb + off.z);
        const uint4 r11 = *reinterpret_cast<const uint4*>(vbb + off.w);
        const __half2* h00 = reinterpret_cast<const __half2*>(&r00);
        const __half2* h01 = reinterpret_cast<const __half2*>(&r01);
        const __half2* h10 = reinterpret_cast<const __half2*>(&r10);
        const __half2* h11 = reinterpret_cast<const __half2*>(&r11);
#pragma unroll
        for (int q = 0; q < 4; ++q) {
            __half2 bl = __hmul2(hw00, h00[q]);
            bl = __hfma2(hw01, h01[q], bl);
            bl = __hfma2(hw10, h10[q], bl);
            bl = __hfma2(hw11, h11[q], bl);
            const float2 f = __half22float2(bl);
            fa[2 * q]     += f.x;
            fa[2 * q + 1] += f.y;
        }
    }
    uint4 st;
    uint32_t* sp = reinterpret_cast<uint32_t*>(&st);
#pragma unroll
    for (int q = 0; q < 4; ++q) {
        const __half2 h = __floats2half2_rn(fa[2 * q], fa[2 * q + 1]);
        sp[q] = *reinterpret_cast<const uint32_t*>(&h);
    }
    *reinterpret_cast<uint4*>(g_agg + ((size_t)pg << 8) + c) = st;
}

// ---------------- launch -----------------------------------------------------
#define SMEM_T0 ((6 * 32 * PADM + 1024) * 4)              // 108544 B
#define SMEM_T1 ((4 * 32 * PADM + 1024 + 2304 + 32) * 4)  // 83072 B
#define SMEM_H  (6 * 128 * PADK * 2)                      // 61440 B

extern "C" void kernel_launch(void* const* d_in, const int* in_sizes, int n_in,
                              void* d_out, int out_size) {
    const float* feats1 = (const float*)d_in[0];
    const float* feats2 = (const float*)d_in[1];
    const float* anchor = (const float*)d_in[2];
    const float* n1g = (const float*)d_in[3];
    const float* n1b = (const float*)d_in[4];
    const float* n2g = (const float*)d_in[5];
    const float* n2b = (const float*)d_in[6];
    const float* Wv  = (const float*)d_in[7];
    const float* bv  = (const float*)d_in[8];
    const float* Ww  = (const float*)d_in[9];
    const float* bw  = (const float*)d_in[10];
    const float* Wk  = (const float*)d_in[11];
    const float* bk  = (const float*)d_in[12];
    const float* Wo  = (const float*)d_in[13];
    const float* bo  = (const float*)d_in[14];

    float* out    = (float*)d_out;
    float* kp_out = out + (size_t)16777216;   // B*C*H*W

    cudaFuncSetAttribute(gemm_tf32<0>, cudaFuncAttributeMaxDynamicSharedMemorySize, SMEM_T0);
    cudaFuncSetAttribute(gemm_tf32<1>, cudaFuncAttributeMaxDynamicSharedMemorySize, SMEM_T1);
    cudaFuncSetAttribute(gemm_f16, cudaFuncAttributeMaxDynamicSharedMemorySize, SMEM_H);

    prep_all<<<258, 256>>>(Wv, n2g, n2b, bv, Wo, n1g, n1b, Ww, bw, Wk, bk);
    gemm_tf32<0><<<dim3(2, 512), 256, SMEM_T0>>>(feats2, nullptr, nullptr, nullptr, nullptr);
    gemm_tf32<1><<<dim3(1, 512), 256, SMEM_T1>>>(feats1, Wk, n1g, anchor, kp_out);
    agg_kernel<<<NPIX / 8, 256>>>(kp_out);
    gemm_f16<<<dim3(2, 512), 256, SMEM_H>>>(bo, out);
}